// round 9
// baseline (speedup 1.0000x reference)
#include <cuda_runtime.h>
#include <cuda_bf16.h>
#include <cstdint>

#define NNODES 50000
#define NEDGES 600000
#define FDIM   128
#define NSCAN_BLOCKS 49      // ceil(50000/1024)
#define CNT_BLOCKS   196     // 196*256 >= 50000

// ---------------------------------------------------------------------------
// Device scratch (no allocations allowed)
// ---------------------------------------------------------------------------
__device__ int   g_cnt[NNODES];          // per-dst degree
__device__ int   g_off[NNODES + 1];      // CSR offsets
__device__ int   g_fill[NNODES];         // running fill pointers
__device__ int   g_srcs[NEDGES];         // src ids sorted by dst
__device__ int   g_bsum[NSCAN_BLOCKS];
__device__ int   g_boff[NSCAN_BLOCKS];
__device__ int   g_ei_is_i64;
// Prepacked per-thread B fragments for m16n8k16 bf16 MMA.
// Layout: [kt (8)][nt (16)][lane (32)] of uint4 {bh0, bh1, bl0, bl1}. 64KB.
__device__ uint4 g_w2frag[8 * 16 * 32];

__device__ __forceinline__ uint32_t pack2_hi(float a, float b) {
    __nv_bfloat162 h = __floats2bfloat162_rn(a, b);
    return *reinterpret_cast<uint32_t*>(&h);
}
__device__ __forceinline__ uint32_t pack2_lo(float a, float b) {
    float la = a - __bfloat162float(__float2bfloat16(a));
    float lb = b - __bfloat162float(__float2bfloat16(b));
    __nv_bfloat162 h = __floats2bfloat162_rn(la, lb);
    return *reinterpret_cast<uint32_t*>(&h);
}

// ---------------------------------------------------------------------------
// prep: blocks [0,16) pack W2 fragments; block 16 probes dtype;
// blocks 17.. zero g_cnt.
// ---------------------------------------------------------------------------
__global__ __launch_bounds__(256)
void prep_kernel(const void* __restrict__ ei, const float* __restrict__ W2) {
    int b = blockIdx.x;
    if (b < 16) {
        int idx = b * 256 + threadIdx.x;      // 0..4095
        int kt = idx >> 9;
        int nt = (idx >> 5) & 15;
        int lane = idx & 31;
        int g = lane >> 2, t = lane & 3;
        int n = nt * 8 + g;
        int kc = kt * 16 + 2 * t;
        float w00 = W2[kc * FDIM + n];
        float w01 = W2[(kc + 1) * FDIM + n];
        float w10 = W2[(kc + 8) * FDIM + n];
        float w11 = W2[(kc + 9) * FDIM + n];
        uint4 f;
        f.x = pack2_hi(w00, w01);
        f.y = pack2_hi(w10, w11);
        f.z = pack2_lo(w00, w01);
        f.w = pack2_lo(w10, w11);
        g_w2frag[idx] = f;
    } else if (b == 16) {
        if (threadIdx.x == 0) {
            const long long* p = (const long long*)ei;
            int ok = 1;
#pragma unroll
            for (int i = 0; i < 16; i++) {
                long long v = p[i];
                if (v < 0 || v >= NNODES) ok = 0;
            }
            g_ei_is_i64 = ok;
        }
    } else {
        int i = (b - 17) * 256 + threadIdx.x;
        if (i < NNODES) g_cnt[i] = 0;
    }
}

// ---------------------------------------------------------------------------
// hist: 4 edges per thread (vectorized dst loads), atomicAdd counts.
// ---------------------------------------------------------------------------
__global__ __launch_bounds__(256)
void hist_kernel(const void* __restrict__ ei) {
    int t4 = blockIdx.x * blockDim.x + threadIdx.x;
    if (t4 >= NEDGES / 4) return;
    if (g_ei_is_i64) {
        const longlong2* p = (const longlong2*)((const long long*)ei + NEDGES);
        longlong2 a = p[t4 * 2], b = p[t4 * 2 + 1];
        atomicAdd(&g_cnt[(int)a.x], 1);
        atomicAdd(&g_cnt[(int)a.y], 1);
        atomicAdd(&g_cnt[(int)b.x], 1);
        atomicAdd(&g_cnt[(int)b.y], 1);
    } else {
        int4 d = ((const int4*)((const int*)ei + NEDGES))[t4];
        atomicAdd(&g_cnt[d.x], 1);
        atomicAdd(&g_cnt[d.y], 1);
        atomicAdd(&g_cnt[d.z], 1);
        atomicAdd(&g_cnt[d.w], 1);
    }
}

// ---------------------------------------------------------------------------
// 2-level exclusive scan over g_cnt -> g_off
// ---------------------------------------------------------------------------
__global__ void scan1_kernel() {  // 49 blocks x 1024
    int tid = threadIdx.x;
    int i = blockIdx.x * 1024 + tid;
    int v = (i < NNODES) ? g_cnt[i] : 0;
    int incl = v;
#pragma unroll
    for (int o = 1; o < 32; o <<= 1) {
        int n = __shfl_up_sync(0xFFFFFFFFu, incl, o);
        if ((tid & 31) >= o) incl += n;
    }
    __shared__ int ws[32];
    if ((tid & 31) == 31) ws[tid >> 5] = incl;
    __syncthreads();
    if (tid < 32) {
        int w = ws[tid];
        int wincl = w;
#pragma unroll
        for (int o = 1; o < 32; o <<= 1) {
            int n = __shfl_up_sync(0xFFFFFFFFu, wincl, o);
            if (tid >= o) wincl += n;
        }
        ws[tid] = wincl - w;
        if (tid == 31) g_bsum[blockIdx.x] = wincl;
    }
    __syncthreads();
    int excl = incl - v + ws[tid >> 5];
    if (i < NNODES) g_off[i] = excl;
}

__global__ void scan2_kernel() {  // 1 block x 64
    int tid = threadIdx.x;
    int v = (tid < NSCAN_BLOCKS) ? g_bsum[tid] : 0;
    int incl = v;
#pragma unroll
    for (int o = 1; o < 32; o <<= 1) {
        int n = __shfl_up_sync(0xFFFFFFFFu, incl, o);
        if ((tid & 31) >= o) incl += n;
    }
    __shared__ int w0tot;
    if (tid == 31) w0tot = incl;
    __syncthreads();
    int excl = incl - v + ((tid >= 32) ? w0tot : 0);
    if (tid < NSCAN_BLOCKS) g_boff[tid] = excl;
}

__global__ void fixup_kernel() {
    int i = blockIdx.x * blockDim.x + threadIdx.x;
    if (i < NNODES) {
        int o = g_off[i] + g_boff[i >> 10];
        g_off[i] = o;
        g_fill[i] = o;
    }
    if (i == 0) g_off[NNODES] = NEDGES;
}

// ---------------------------------------------------------------------------
// reorder: 4 edges per thread; src ids bucketed by dst.
// ---------------------------------------------------------------------------
__global__ __launch_bounds__(256)
void reorder_kernel(const void* __restrict__ ei) {
    int t4 = blockIdx.x * blockDim.x + threadIdx.x;
    if (t4 >= NEDGES / 4) return;
    int s[4], d[4];
    if (g_ei_is_i64) {
        const longlong2* ps = (const longlong2*)ei;
        const longlong2* pd = (const longlong2*)((const long long*)ei + NEDGES);
        longlong2 s0 = ps[t4 * 2], s1 = ps[t4 * 2 + 1];
        longlong2 d0 = pd[t4 * 2], d1 = pd[t4 * 2 + 1];
        s[0] = (int)s0.x; s[1] = (int)s0.y; s[2] = (int)s1.x; s[3] = (int)s1.y;
        d[0] = (int)d0.x; d[1] = (int)d0.y; d[2] = (int)d1.x; d[3] = (int)d1.y;
    } else {
        int4 sv = ((const int4*)ei)[t4];
        int4 dv = ((const int4*)((const int*)ei + NEDGES))[t4];
        s[0] = sv.x; s[1] = sv.y; s[2] = sv.z; s[3] = sv.w;
        d[0] = dv.x; d[1] = dv.y; d[2] = dv.z; d[3] = dv.w;
    }
#pragma unroll
    for (int j = 0; j < 4; j++) {
        int pos = atomicAdd(&g_fill[d[j]], 1);
        g_srcs[pos] = s[j];
    }
}

// ---------------------------------------------------------------------------
// Fused aggregate + GEMM. CTA = 128 dst rows. Phase 1: each warp CSR-
// aggregates 16 rows into a 64KB xor-swizzled smem tile. Phase 2: bf16x3
// mma.sync from smem A + prepacked global B fragments. C = A@W2 + bias.
// smem col swizzle: col' = col ^ (8*(row&7))  (float granularity)
// ---------------------------------------------------------------------------
__device__ __forceinline__ void mma_bf16(float* c, uint32_t a0, uint32_t a1,
                                         uint32_t a2, uint32_t a3,
                                         uint32_t b0, uint32_t b1) {
    asm volatile(
        "mma.sync.aligned.m16n8k16.row.col.f32.bf16.bf16.f32 "
        "{%0,%1,%2,%3}, {%4,%5,%6,%7}, {%8,%9}, {%0,%1,%2,%3};"
        : "+f"(c[0]), "+f"(c[1]), "+f"(c[2]), "+f"(c[3])
        : "r"(a0), "r"(a1), "r"(a2), "r"(a3), "r"(b0), "r"(b1));
}

__global__ __launch_bounds__(256)
void fused_kernel(const float* __restrict__ x,
                  const float* __restrict__ bias,
                  float* __restrict__ C) {
    extern __shared__ float sA[];   // 128 x 128 f32, swizzled
    const int lane = threadIdx.x & 31;
    const int wid  = threadIdx.x >> 5;
    const int row0 = blockIdx.x * 128;

    // ---- Phase 1: aggregate 16 rows per warp ----
#pragma unroll 1
    for (int rl = 0; rl < 16; rl++) {
        int lr = wid * 16 + rl;          // local row 0..127
        int node = row0 + lr;
        float4 acc = make_float4(0.f, 0.f, 0.f, 0.f);
        if (node < NNODES) {
            int beg = g_off[node], end = g_off[node + 1];
            int i = beg;
            for (; i + 1 < end; i += 2) {
                int s0 = g_srcs[i], s1 = g_srcs[i + 1];
                float4 v0 = *reinterpret_cast<const float4*>(&x[(size_t)s0 * FDIM + lane * 4]);
                float4 v1 = *reinterpret_cast<const float4*>(&x[(size_t)s1 * FDIM + lane * 4]);
                acc.x += v0.x + v1.x; acc.y += v0.y + v1.y;
                acc.z += v0.z + v1.z; acc.w += v0.w + v1.w;
            }
            if (i < end) {
                int s0 = g_srcs[i];
                float4 v0 = *reinterpret_cast<const float4*>(&x[(size_t)s0 * FDIM + lane * 4]);
                acc.x += v0.x; acc.y += v0.y; acc.z += v0.z; acc.w += v0.w;
            }
        }
        int col = (4 * lane) ^ (8 * (lr & 7));
        *reinterpret_cast<float4*>(&sA[lr * FDIM + col]) = acc;
    }
    __syncthreads();

    // ---- Phase 2: MMA from smem ----
    const int g = lane >> 2;      // 0..7
    const int t = lane & 3;       // 0..3
    const int lr0 = wid * 16 + g;
    const int lr1 = lr0 + 8;
    const int sw0 = 8 * (lr0 & 7);
    const int sw1 = 8 * (lr1 & 7);

    float acc[16][4];
#pragma unroll
    for (int nt = 0; nt < 16; nt++)
#pragma unroll
        for (int j = 0; j < 4; j++) acc[nt][j] = 0.f;

#pragma unroll 1
    for (int kt = 0; kt < 8; kt++) {
        const int k0 = kt * 16;
        float2 f0 = *reinterpret_cast<const float2*>(&sA[lr0 * FDIM + ((k0 + 2 * t) ^ sw0)]);
        float2 f2 = *reinterpret_cast<const float2*>(&sA[lr0 * FDIM + ((k0 + 2 * t + 8) ^ sw0)]);
        float2 f1 = *reinterpret_cast<const float2*>(&sA[lr1 * FDIM + ((k0 + 2 * t) ^ sw1)]);
        float2 f3 = *reinterpret_cast<const float2*>(&sA[lr1 * FDIM + ((k0 + 2 * t + 8) ^ sw1)]);
        uint32_t ah0 = pack2_hi(f0.x, f0.y), ah1 = pack2_hi(f1.x, f1.y);
        uint32_t ah2 = pack2_hi(f2.x, f2.y), ah3 = pack2_hi(f3.x, f3.y);
        uint32_t al0 = pack2_lo(f0.x, f0.y), al1 = pack2_lo(f1.x, f1.y);
        uint32_t al2 = pack2_lo(f2.x, f2.y), al3 = pack2_lo(f3.x, f3.y);

        const uint4* bp = &g_w2frag[(kt * 16) * 32 + lane];
#pragma unroll
        for (int nt = 0; nt < 16; nt++) {
            uint4 bfrag = bp[nt * 32];   // one LDG.128, L1-resident
            mma_bf16(acc[nt], ah0, ah1, ah2, ah3, bfrag.x, bfrag.y);
            mma_bf16(acc[nt], ah0, ah1, ah2, ah3, bfrag.z, bfrag.w);
            mma_bf16(acc[nt], al0, al1, al2, al3, bfrag.x, bfrag.y);
        }
    }

    const int r0 = row0 + lr0;
    const int r1 = row0 + lr1;
#pragma unroll
    for (int nt = 0; nt < 16; nt++) {
        const int c = nt * 8 + 2 * t;
        float bx = __ldg(&bias[c]);
        float by = __ldg(&bias[c + 1]);
        if (r0 < NNODES) {
            float2 o = make_float2(acc[nt][0] + bx, acc[nt][1] + by);
            *reinterpret_cast<float2*>(&C[(size_t)r0 * FDIM + c]) = o;
        }
        if (r1 < NNODES) {
            float2 o = make_float2(acc[nt][2] + bx, acc[nt][3] + by);
            *reinterpret_cast<float2*>(&C[(size_t)r1 * FDIM + c]) = o;
        }
    }
}

// ---------------------------------------------------------------------------
// kernel_launch
// Inputs: 0:x, 1:edge_index, 2:edge_weight(u), 3:W1(u), 4:b1(u),
//         5:W2, 6:b2, 7:a(u), 8:b(u).  Output: [N,128] f32
// ---------------------------------------------------------------------------
extern "C" void kernel_launch(void* const* d_in, const int* in_sizes, int n_in,
                              void* d_out, int out_size) {
    const float* x   = (const float*)d_in[0];
    const void*  ei  = d_in[1];
    const float* W2  = (const float*)d_in[5];
    const float* b2  = (const float*)d_in[6];
    float*       out = (float*)d_out;

    cudaFuncSetAttribute(fused_kernel, cudaFuncAttributeMaxDynamicSharedMemorySize,
                         FDIM * FDIM * (int)sizeof(float));

    prep_kernel<<<17 + CNT_BLOCKS, 256>>>(ei, W2);
    hist_kernel<<<(NEDGES / 4 + 255) / 256, 256>>>(ei);
    scan1_kernel<<<NSCAN_BLOCKS, 1024>>>();
    scan2_kernel<<<1, 64>>>();
    fixup_kernel<<<NSCAN_BLOCKS, 1024>>>();
    reorder_kernel<<<(NEDGES / 4 + 255) / 256, 256>>>(ei);
    fused_kernel<<<(NNODES + 127) / 128, 256, FDIM * FDIM * sizeof(float)>>>(x, b2, out);
}